// round 1
// baseline (speedup 1.0000x reference)
#include <cuda_runtime.h>

#define N_NODES 20000
#define N_EDGES 320000
#define F 512
#define F4 128
#define DT 0.2f
#define TDECAY 0.1f
#define LN_EPS 1e-5f

// ---- static device scratch (no dynamic allocation allowed) ----
__device__ float g_w[N_EDGES];
__device__ float g_degw[N_NODES];
__device__ float g_dinv[N_NODES];
__device__ int   g_cnt[N_NODES];
__device__ int   g_rowptr[N_NODES + 1];
__device__ int   g_cursor[N_NODES];
__device__ int   g_srcs[N_EDGES];
__device__ float g_ews[N_EDGES];
__device__ float g_ha[(size_t)N_NODES * F];
__device__ float g_hb[(size_t)N_NODES * F];
__device__ unsigned g_tmax_bits;

// graph_time arrives as a scalar; robust to int32/int64/float32 encodings.
__device__ __forceinline__ float decode_gt(const void* p) {
    int iv = *(const int*)p;
    if (iv >= 0 && iv < (1 << 24)) return (float)iv;
    return *(const float*)p;
}

// ---- preprocessing kernels ----
__global__ void k_init(const void* gt_ptr) {
    int i = blockIdx.x * blockDim.x + threadIdx.x;
    if (i < N_NODES) { g_cnt[i] = 0; g_degw[i] = 0.f; }
    if (i == 0) g_tmax_bits = __float_as_uint(decode_gt(gt_ptr));  // ts >= 0 so uint-ordered
}

__global__ void k_pass1(const int* __restrict__ ei, const float* __restrict__ ts) {
    int e = blockIdx.x * blockDim.x + threadIdx.x;
    if (e >= N_EDGES) return;
    atomicMax(&g_tmax_bits, __float_as_uint(ts[e]));
    atomicAdd(&g_cnt[ei[N_EDGES + e]], 1);
}

__global__ void k_weights(const int* __restrict__ ei, const float* __restrict__ ts) {
    int e = blockIdx.x * blockDim.x + threadIdx.x;
    if (e >= N_EDGES) return;
    float tmax = __uint_as_float(g_tmax_bits);
    float w = expf(-TDECAY * (tmax - ts[e]));
    g_w[e] = w;
    atomicAdd(&g_degw[ei[N_EDGES + e]], w);
}

__global__ void k_dinv(const void* gt_ptr) {
    int i = blockIdx.x * blockDim.x + threadIdx.x;
    if (i >= N_NODES) return;
    float tmax = __uint_as_float(g_tmax_bits);
    float self_w = expf(-TDECAY * (tmax - decode_gt(gt_ptr)));
    float tot = g_degw[i] + self_w;   // self-loop contributes to degree
    g_dinv[i] = (tot > 0.f) ? (1.f / sqrtf(tot)) : 0.f;
}

__global__ void k_scan() {  // one block, 1024 threads: exclusive scan of g_cnt -> rowptr/cursor
    __shared__ int sh[1024];
    int t = threadIdx.x;
    const int CH = 20;  // 1024*20 >= 20000
    int beg = t * CH;
    int lsum = 0;
    for (int i = 0; i < CH; i++) {
        int idx = beg + i;
        if (idx < N_NODES) lsum += g_cnt[idx];
    }
    sh[t] = lsum;
    __syncthreads();
    for (int off = 1; off < 1024; off <<= 1) {
        int v = 0;
        if (t >= off) v = sh[t - off];
        __syncthreads();
        sh[t] += v;
        __syncthreads();
    }
    int run = sh[t] - lsum;  // exclusive prefix
    for (int i = 0; i < CH; i++) {
        int idx = beg + i;
        if (idx < N_NODES) {
            g_rowptr[idx] = run;
            g_cursor[idx] = run;
            run += g_cnt[idx];
        }
    }
    if (t == 1023) g_rowptr[N_NODES] = sh[1023];
}

__global__ void k_fill(const int* __restrict__ ei) {
    int e = blockIdx.x * blockDim.x + threadIdx.x;
    if (e >= N_EDGES) return;
    int src = ei[e], dst = ei[N_EDGES + e];
    int p = atomicAdd(&g_cursor[dst], 1);
    g_srcs[p] = src;
    g_ews[p] = g_dinv[src] * g_w[e] * g_dinv[dst];
}

// ---- diffusion SpMM: one block per dst node, 128 threads x float4 ----
__global__ __launch_bounds__(128) void k_spmm(int step, const float* __restrict__ x,
                                              const void* gt_ptr) {
    const float* hin = (step == 0) ? x : ((step & 1) ? g_ha : g_hb);
    float* hout = (step & 1) ? g_hb : g_ha;
    int n = blockIdx.x;
    int t = threadIdx.x;

    float tmax = __uint_as_float(g_tmax_bits);
    float self_w = expf(-TDECAY * (tmax - decode_gt(gt_ptr)));
    float dv = g_dinv[n];
    // h_new = (1-dt)h + dt*(self_ew*h + sum ew*h[src]);  self_ew = dinv^2 * self_w
    float coef = (1.f - DT) + DT * self_w * dv * dv;

    const float4* hin4 = (const float4*)hin;
    float4 hv = hin4[(size_t)n * F4 + t];
    float4 acc;
    acc.x = coef * hv.x; acc.y = coef * hv.y; acc.z = coef * hv.z; acc.w = coef * hv.w;

    int beg = g_rowptr[n], end = g_rowptr[n + 1];
    __shared__ int s_src[128];
    __shared__ float s_ew[128];
    for (int base = beg; base < end; base += 128) {
        int cnt = min(128, end - base);
        if (t < cnt) {
            s_src[t] = g_srcs[base + t];
            s_ew[t] = DT * g_ews[base + t];
        }
        __syncthreads();
        int j = 0;
        for (; j + 4 <= cnt; j += 4) {
            int   s0 = s_src[j], s1 = s_src[j+1], s2 = s_src[j+2], s3 = s_src[j+3];
            float w0 = s_ew[j],  w1 = s_ew[j+1],  w2 = s_ew[j+2],  w3 = s_ew[j+3];
            float4 v0 = hin4[(size_t)s0 * F4 + t];
            float4 v1 = hin4[(size_t)s1 * F4 + t];
            float4 v2 = hin4[(size_t)s2 * F4 + t];
            float4 v3 = hin4[(size_t)s3 * F4 + t];
            acc.x += w0*v0.x + w1*v1.x + w2*v2.x + w3*v3.x;
            acc.y += w0*v0.y + w1*v1.y + w2*v2.y + w3*v3.y;
            acc.z += w0*v0.z + w1*v1.z + w2*v2.z + w3*v3.z;
            acc.w += w0*v0.w + w1*v1.w + w2*v2.w + w3*v3.w;
        }
        for (; j < cnt; j++) {
            float w = s_ew[j];
            float4 v = hin4[(size_t)s_src[j] * F4 + t];
            acc.x += w*v.x; acc.y += w*v.y; acc.z += w*v.z; acc.w += w*v.w;
        }
        __syncthreads();
    }
    ((float4*)hout)[(size_t)n * F4 + t] = acc;
}

// ---- fp32 SGEMM: C[M,512] = A[M,512] @ W[512,512]^T ; 128x128x8 tile, 8x8/thread ----
// mode 0: A = g_ha, C = g_hb (plain)
// mode 1: A = Aext(x), C = Cext(out), epilogue: C = relu(G1 + bias) + acc, G1 = g_hb
__global__ __launch_bounds__(256, 2) void k_gemm(int mode, const float* __restrict__ Aext,
                                                 const float* __restrict__ W,
                                                 const float* __restrict__ bias,
                                                 float* __restrict__ Cext) {
    const float* A = mode ? Aext : g_ha;
    const float* G1 = g_hb;
    float* C = mode ? Cext : g_hb;
    const int M = N_NODES;

    __shared__ float As[8][128];
    __shared__ float Bs[8][128];

    int t = threadIdx.x;
    int bm = blockIdx.x, bn = blockIdx.y;
    int lrow = t >> 1;
    int kq = (t & 1) * 4;
    int arow = bm * 128 + lrow;
    int wrow = bn * 128 + lrow;  // always < 512

    float acc[8][8];
#pragma unroll
    for (int i = 0; i < 8; i++)
#pragma unroll
        for (int j = 0; j < 8; j++) acc[i][j] = 0.f;

    const float* Aptr = A + (size_t)arow * F + kq;
    const float* Wptr = W + (size_t)wrow * F + kq;
    int tm = (t >> 4) * 8, tn = (t & 15) * 8;

    for (int k0 = 0; k0 < F; k0 += 8) {
        float4 av = (arow < M) ? *(const float4*)(Aptr + k0) : make_float4(0.f, 0.f, 0.f, 0.f);
        float4 wv = *(const float4*)(Wptr + k0);
        As[kq + 0][lrow] = av.x; As[kq + 1][lrow] = av.y;
        As[kq + 2][lrow] = av.z; As[kq + 3][lrow] = av.w;
        Bs[kq + 0][lrow] = wv.x; Bs[kq + 1][lrow] = wv.y;
        Bs[kq + 2][lrow] = wv.z; Bs[kq + 3][lrow] = wv.w;
        __syncthreads();
#pragma unroll
        for (int kk = 0; kk < 8; kk++) {
            float a[8], b[8];
            *(float4*)&a[0] = *(const float4*)&As[kk][tm];
            *(float4*)&a[4] = *(const float4*)&As[kk][tm + 4];
            *(float4*)&b[0] = *(const float4*)&Bs[kk][tn];
            *(float4*)&b[4] = *(const float4*)&Bs[kk][tn + 4];
#pragma unroll
            for (int i = 0; i < 8; i++)
#pragma unroll
                for (int j = 0; j < 8; j++) acc[i][j] += a[i] * b[j];
        }
        __syncthreads();
    }

#pragma unroll
    for (int i = 0; i < 8; i++) {
        int row = bm * 128 + tm + i;
        if (row >= M) break;
        int col = bn * 128 + tn;
        float* crow = C + (size_t)row * F + col;
        if (mode) {
            const float* g = G1 + (size_t)row * F + col;
            float4 g0 = *(const float4*)(g);
            float4 g1 = *(const float4*)(g + 4);
            float4 b0 = *(const float4*)(bias + col);
            float4 b1 = *(const float4*)(bias + col + 4);
            float4 o0, o1;
            o0.x = fmaxf(g0.x + b0.x, 0.f) + acc[i][0];
            o0.y = fmaxf(g0.y + b0.y, 0.f) + acc[i][1];
            o0.z = fmaxf(g0.z + b0.z, 0.f) + acc[i][2];
            o0.w = fmaxf(g0.w + b0.w, 0.f) + acc[i][3];
            o1.x = fmaxf(g1.x + b1.x, 0.f) + acc[i][4];
            o1.y = fmaxf(g1.y + b1.y, 0.f) + acc[i][5];
            o1.z = fmaxf(g1.z + b1.z, 0.f) + acc[i][6];
            o1.w = fmaxf(g1.w + b1.w, 0.f) + acc[i][7];
            *(float4*)(crow) = o0;
            *(float4*)(crow + 4) = o1;
        } else {
            float4 o0, o1;
            o0.x = acc[i][0]; o0.y = acc[i][1]; o0.z = acc[i][2]; o0.w = acc[i][3];
            o1.x = acc[i][4]; o1.y = acc[i][5]; o1.z = acc[i][6]; o1.w = acc[i][7];
            *(float4*)(crow) = o0;
            *(float4*)(crow + 4) = o1;
        }
    }
}

// ---- row LayerNorm in place: 128 threads x float4 per row ----
__global__ __launch_bounds__(128) void k_ln(float* __restrict__ out,
                                            const float* __restrict__ gamma,
                                            const float* __restrict__ beta) {
    int n = blockIdx.x;
    int t = threadIdx.x;
    float4* row = (float4*)(out + (size_t)n * F);
    float4 v = row[t];
    float s = v.x + v.y + v.z + v.w;
    float q = v.x * v.x + v.y * v.y + v.z * v.z + v.w * v.w;
#pragma unroll
    for (int o = 16; o; o >>= 1) {
        s += __shfl_xor_sync(0xffffffffu, s, o);
        q += __shfl_xor_sync(0xffffffffu, q, o);
    }
    __shared__ float shs[4], shq[4];
    int w = t >> 5, l = t & 31;
    if (l == 0) { shs[w] = s; shq[w] = q; }
    __syncthreads();
    s = shs[0] + shs[1] + shs[2] + shs[3];
    q = shq[0] + shq[1] + shq[2] + shq[3];
    float mu = s * (1.f / F);
    float var = q * (1.f / F) - mu * mu;
    float inv = rsqrtf(var + LN_EPS);
    float4 gv = ((const float4*)gamma)[t];
    float4 bv = ((const float4*)beta)[t];
    v.x = (v.x - mu) * inv * gv.x + bv.x;
    v.y = (v.y - mu) * inv * gv.y + bv.y;
    v.z = (v.z - mu) * inv * gv.z + bv.z;
    v.w = (v.w - mu) * inv * gv.w + bv.w;
    row[t] = v;
}

extern "C" void kernel_launch(void* const* d_in, const int* in_sizes, int n_in,
                              void* d_out, int out_size) {
    const float* x = (const float*)d_in[0];      // [20000, 512]
    const int* ei = (const int*)d_in[1];         // [2, 320000]
    const float* ts = (const float*)d_in[2];     // [320000]
    const float* W_t = (const float*)d_in[3];    // [512, 512]
    const float* b_t = (const float*)d_in[4];    // [512]
    const float* W_r = (const float*)d_in[5];    // [512, 512]
    const float* gamma = (const float*)d_in[6];  // [512]
    const float* beta = (const float*)d_in[7];   // [512]
    const void* gt = d_in[8];                    // scalar graph_time
    float* out = (float*)d_out;

    k_init<<<(N_NODES + 255) / 256, 256>>>(gt);
    k_pass1<<<(N_EDGES + 255) / 256, 256>>>(ei, ts);
    k_weights<<<(N_EDGES + 255) / 256, 256>>>(ei, ts);
    k_dinv<<<(N_NODES + 255) / 256, 256>>>(gt);
    k_scan<<<1, 1024>>>();
    k_fill<<<(N_EDGES + 255) / 256, 256>>>(ei);

    for (int s = 0; s < 5; s++) k_spmm<<<N_NODES, 128>>>(s, x, gt);

    dim3 gg((N_NODES + 127) / 128, F / 128);
    k_gemm<<<gg, 256>>>(0, nullptr, W_t, nullptr, nullptr);  // G1 = h @ W_t^T -> g_hb
    k_gemm<<<gg, 256>>>(1, x, W_r, b_t, out);                // out = relu(G1+b) + x @ W_r^T
    k_ln<<<N_NODES, 128>>>(out, gamma, beta);
}

// round 3
// speedup vs baseline: 1.7633x; 1.7633x over previous
#include <cuda_runtime.h>
#include <cuda_bf16.h>
#include <cstdint>

#define N_NODES 20000
#define N_EDGES 320000
#define F 512
#define F4 128
#define DT 0.2f
#define TDECAY 0.1f
#define LN_EPS 1e-5f

// ---- GEMM tiling (mma.sync bf16-split) ----
#define TILE_M 128
#define TILE_N 128
#define KCHUNK 32
#define NCHUNK (F / KCHUNK)          // 16
#define ROWB 80                       // padded smem row stride in bytes (32 bf16 + pad)
#define HALF_SZ (128 * ROWB)          // 10240 bytes, one hi or lo tile
#define AB_SZ (2 * HALF_SZ)           // A(hi+lo) = 20480
#define BUF_SZ (2 * AB_SZ)            // A + B = 40960
#define SMEM_DYN (2 * BUF_SZ)         // double buffered = 81920

// ---- static device scratch ----
__device__ float g_w[N_EDGES];
__device__ float g_degw[N_NODES];
__device__ float g_dinv[N_NODES];
__device__ int   g_cnt[N_NODES];
__device__ int   g_rowptr[N_NODES + 1];
__device__ int   g_cursor[N_NODES];
__device__ int   g_srcs[N_EDGES];
__device__ float g_ews[N_EDGES];
__device__ float g_ha[(size_t)N_NODES * F];
__device__ float g_hb[(size_t)N_NODES * F];
__device__ unsigned g_tmax_bits;

// ---------------- helpers ----------------
__device__ __forceinline__ uint32_t smem_u32(const void* p) {
    uint32_t a;
    asm("{ .reg .u64 t; cvta.to.shared.u64 t, %1; cvt.u32.u64 %0, t; }" : "=r"(a) : "l"(p));
    return a;
}
__device__ __forceinline__ void ldsm4(unsigned* r, uint32_t addr) {
    asm volatile("ldmatrix.sync.aligned.m8n8.x4.shared.b16 {%0,%1,%2,%3}, [%4];"
                 : "=r"(r[0]), "=r"(r[1]), "=r"(r[2]), "=r"(r[3]) : "r"(addr));
}
__device__ __forceinline__ void mma_bf16(float* d, const unsigned* a, unsigned b0, unsigned b1) {
    asm volatile(
        "mma.sync.aligned.m16n8k16.row.col.f32.bf16.bf16.f32 "
        "{%0,%1,%2,%3}, {%4,%5,%6,%7}, {%8,%9}, {%0,%1,%2,%3};"
        : "+f"(d[0]), "+f"(d[1]), "+f"(d[2]), "+f"(d[3])
        : "r"(a[0]), "r"(a[1]), "r"(a[2]), "r"(a[3]), "r"(b0), "r"(b1));
}
__device__ __forceinline__ unsigned pack_bf16(float a, float b) {
    __nv_bfloat162 p = __floats2bfloat162_rn(a, b);
    return *reinterpret_cast<unsigned*>(&p);
}
// graph_time arrives as a scalar; robust to int32/int64/float32 encodings.
__device__ __forceinline__ float decode_gt(const void* p) {
    int iv = *(const int*)p;
    if (iv >= 0 && iv < (1 << 24)) return (float)iv;
    return *(const float*)p;
}

// ---- preprocessing kernels ----
__global__ void k_init(const void* gt_ptr) {
    int i = blockIdx.x * blockDim.x + threadIdx.x;
    if (i < N_NODES) { g_cnt[i] = 0; g_degw[i] = 0.f; }
    if (i == 0) g_tmax_bits = __float_as_uint(decode_gt(gt_ptr));
}

__global__ void k_pass1(const int* __restrict__ ei, const float* __restrict__ ts) {
    int e = blockIdx.x * blockDim.x + threadIdx.x;
    if (e >= N_EDGES) return;
    atomicMax(&g_tmax_bits, __float_as_uint(ts[e]));
    atomicAdd(&g_cnt[ei[N_EDGES + e]], 1);
}

__global__ void k_weights(const int* __restrict__ ei, const float* __restrict__ ts) {
    int e = blockIdx.x * blockDim.x + threadIdx.x;
    if (e >= N_EDGES) return;
    float tmax = __uint_as_float(g_tmax_bits);
    float w = expf(-TDECAY * (tmax - ts[e]));
    g_w[e] = w;
    atomicAdd(&g_degw[ei[N_EDGES + e]], w);
}

__global__ void k_dinv(const void* gt_ptr) {
    int i = blockIdx.x * blockDim.x + threadIdx.x;
    if (i >= N_NODES) return;
    float tmax = __uint_as_float(g_tmax_bits);
    float self_w = expf(-TDECAY * (tmax - decode_gt(gt_ptr)));
    float tot = g_degw[i] + self_w;
    g_dinv[i] = (tot > 0.f) ? (1.f / sqrtf(tot)) : 0.f;
}

__global__ void k_scan() {
    __shared__ int sh[1024];
    int t = threadIdx.x;
    const int CH = 20;
    int beg = t * CH;
    int lsum = 0;
    for (int i = 0; i < CH; i++) {
        int idx = beg + i;
        if (idx < N_NODES) lsum += g_cnt[idx];
    }
    sh[t] = lsum;
    __syncthreads();
    for (int off = 1; off < 1024; off <<= 1) {
        int v = 0;
        if (t >= off) v = sh[t - off];
        __syncthreads();
        sh[t] += v;
        __syncthreads();
    }
    int run = sh[t] - lsum;
    for (int i = 0; i < CH; i++) {
        int idx = beg + i;
        if (idx < N_NODES) {
            g_rowptr[idx] = run;
            g_cursor[idx] = run;
            run += g_cnt[idx];
        }
    }
    if (t == 1023) g_rowptr[N_NODES] = sh[1023];
}

__global__ void k_fill(const int* __restrict__ ei) {
    int e = blockIdx.x * blockDim.x + threadIdx.x;
    if (e >= N_EDGES) return;
    int src = ei[e], dst = ei[N_EDGES + e];
    int p = atomicAdd(&g_cursor[dst], 1);
    g_srcs[p] = src;
    g_ews[p] = g_dinv[src] * g_w[e] * g_dinv[dst];
}

// ---- diffusion SpMM ----
__global__ __launch_bounds__(128) void k_spmm(int step, const float* __restrict__ x,
                                              const void* gt_ptr) {
    const float* hin = (step == 0) ? x : ((step & 1) ? g_ha : g_hb);
    float* hout = (step & 1) ? g_hb : g_ha;
    int n = blockIdx.x;
    int t = threadIdx.x;

    float tmax = __uint_as_float(g_tmax_bits);
    float self_w = expf(-TDECAY * (tmax - decode_gt(gt_ptr)));
    float dv = g_dinv[n];
    float coef = (1.f - DT) + DT * self_w * dv * dv;

    const float4* hin4 = (const float4*)hin;
    float4 hv = hin4[(size_t)n * F4 + t];
    float4 acc;
    acc.x = coef * hv.x; acc.y = coef * hv.y; acc.z = coef * hv.z; acc.w = coef * hv.w;

    int beg = g_rowptr[n], end = g_rowptr[n + 1];
    __shared__ int s_src[128];
    __shared__ float s_ew[128];
    for (int base = beg; base < end; base += 128) {
        int cnt = min(128, end - base);
        if (t < cnt) {
            s_src[t] = g_srcs[base + t];
            s_ew[t] = DT * g_ews[base + t];
        }
        __syncthreads();
        int j = 0;
        for (; j + 4 <= cnt; j += 4) {
            int   s0 = s_src[j], s1 = s_src[j+1], s2 = s_src[j+2], s3 = s_src[j+3];
            float w0 = s_ew[j],  w1 = s_ew[j+1],  w2 = s_ew[j+2],  w3 = s_ew[j+3];
            float4 v0 = hin4[(size_t)s0 * F4 + t];
            float4 v1 = hin4[(size_t)s1 * F4 + t];
            float4 v2 = hin4[(size_t)s2 * F4 + t];
            float4 v3 = hin4[(size_t)s3 * F4 + t];
            acc.x += w0*v0.x + w1*v1.x + w2*v2.x + w3*v3.x;
            acc.y += w0*v0.y + w1*v1.y + w2*v2.y + w3*v3.y;
            acc.z += w0*v0.z + w1*v1.z + w2*v2.z + w3*v3.z;
            acc.w += w0*v0.w + w1*v1.w + w2*v2.w + w3*v3.w;
        }
        for (; j < cnt; j++) {
            float w = s_ew[j];
            float4 v = hin4[(size_t)s_src[j] * F4 + t];
            acc.x += w*v.x; acc.y += w*v.y; acc.z += w*v.z; acc.w += w*v.w;
        }
        __syncthreads();
    }
    ((float4*)hout)[(size_t)n * F4 + t] = acc;
}

// ---- load one 128x32 fp32 tile, convert to bf16 hi/lo into padded smem ----
__device__ __forceinline__ void load_tile(char* dstHi, char* dstLo,
                                          const float* __restrict__ g,
                                          int row0, int rowMax, int k0, int t) {
    // 512 slots: slot = row*4 + kgroup(8 floats)
#pragma unroll
    for (int it = 0; it < 2; it++) {
        int s = t + it * 256;
        int row = s >> 2;
        int kg = (s & 3) * 8;
        int grow = row0 + row;
        float4 v0, v1;
        if (grow < rowMax) {
            const float* p = g + (size_t)grow * F + k0 + kg;
            v0 = *(const float4*)p;
            v1 = *(const float4*)(p + 4);
        } else {
            v0 = make_float4(0.f, 0.f, 0.f, 0.f);
            v1 = v0;
        }
        float f[8] = {v0.x, v0.y, v0.z, v0.w, v1.x, v1.y, v1.z, v1.w};
        unsigned hi[4], lo[4];
#pragma unroll
        for (int i = 0; i < 4; i++) {
            float a = f[2 * i], b = f[2 * i + 1];
            float ah = __bfloat162float(__float2bfloat16(a));
            float bh = __bfloat162float(__float2bfloat16(b));
            hi[i] = pack_bf16(a, b);
            lo[i] = pack_bf16(a - ah, b - bh);
        }
        unsigned off = row * ROWB + kg * 2;
        *(uint4*)(dstHi + off) = make_uint4(hi[0], hi[1], hi[2], hi[3]);
        *(uint4*)(dstLo + off) = make_uint4(lo[0], lo[1], lo[2], lo[3]);
    }
}

// ---- split-bf16 mma.sync GEMM: C[M,512] = A[M,512] @ W[512,512]^T ----
// mode 0: A=g_ha, C=g_hb (raw).  mode 1: A=Aext, epilogue relu(g_hb+bias)+acc -> Cext
__global__ __launch_bounds__(256, 2) void k_gemm_mma(int mode, const float* __restrict__ Aext,
                                                     const float* __restrict__ W,
                                                     const float* __restrict__ bias,
                                                     float* __restrict__ Cext) {
    extern __shared__ char smd[];
    const float* A = mode ? Aext : g_ha;
    float* C = mode ? Cext : g_hb;

    int t = threadIdx.x, lane = t & 31, wid = t >> 5;
    int wm = wid >> 1, wn = wid & 1;       // warp tile: rows wm*32, cols wn*64
    int bm = blockIdx.x, bn = blockIdx.y;

    // ldmatrix lane→address components (x4: tile = lane/8)
    int lr8 = lane & 7, lt = lane >> 3;
    int row_off = lr8 + (lt & 1) * 8;      // row within 16
    int col_off = (lt >> 1) * 8;           // k within 16

    float acc[2][8][4];
#pragma unroll
    for (int i = 0; i < 2; i++)
#pragma unroll
        for (int j = 0; j < 8; j++)
#pragma unroll
            for (int q = 0; q < 4; q++) acc[i][j][q] = 0.f;

    // preload chunk 0
    load_tile(smd, smd + HALF_SZ, A, bm * TILE_M, N_NODES, 0, t);
    load_tile(smd + AB_SZ, smd + AB_SZ + HALF_SZ, W, bn * TILE_N, F, 0, t);
    __syncthreads();

    for (int c = 0; c < NCHUNK; c++) {
        char* cur = smd + (c & 1) * BUF_SZ;
        if (c + 1 < NCHUNK) {
            char* nxt = smd + ((c + 1) & 1) * BUF_SZ;
            load_tile(nxt, nxt + HALF_SZ, A, bm * TILE_M, N_NODES, (c + 1) * KCHUNK, t);
            load_tile(nxt + AB_SZ, nxt + AB_SZ + HALF_SZ, W, bn * TILE_N, F, (c + 1) * KCHUNK, t);
        }
        uint32_t sA = smem_u32(cur);
        uint32_t sB = sA + AB_SZ;
#pragma unroll
        for (int pass = 0; pass < 3; pass++) {
            uint32_t aBase = sA + ((pass == 2) ? HALF_SZ : 0);
            uint32_t bBase = sB + ((pass == 1) ? HALF_SZ : 0);
#pragma unroll
            for (int ks = 0; ks < 2; ks++) {
                unsigned af[2][4];
#pragma unroll
                for (int mt = 0; mt < 2; mt++)
                    ldsm4(af[mt], aBase + (wm * 32 + mt * 16 + row_off) * ROWB
                                        + (ks * 16 + col_off) * 2);
                unsigned bf[4][4];
#pragma unroll
                for (int pr = 0; pr < 4; pr++)
                    ldsm4(bf[pr], bBase + (wn * 64 + pr * 16 + row_off) * ROWB
                                        + (ks * 16 + col_off) * 2);
#pragma unroll
                for (int mt = 0; mt < 2; mt++)
#pragma unroll
                    for (int nt = 0; nt < 8; nt++) {
                        int pr = nt >> 1, h = nt & 1;
                        mma_bf16(acc[mt][nt], af[mt], bf[pr][h], bf[pr][h + 2]);
                    }
            }
        }
        __syncthreads();
    }

    // epilogue: thread owns C[row = .. + lane/4 (+8)][col = .. + 2*(lane%4)] pairs
    int rbase = bm * TILE_M + wm * 32 + (lane >> 2);
    int cbase = bn * TILE_N + wn * 64 + 2 * (lane & 3);
#pragma unroll
    for (int mt = 0; mt < 2; mt++) {
#pragma unroll
        for (int h = 0; h < 2; h++) {
            int row = rbase + mt * 16 + h * 8;
            if (row >= N_NODES) continue;
            float* crow = C + (size_t)row * F;
            const float* grow = g_hb + (size_t)row * F;
#pragma unroll
            for (int nt = 0; nt < 8; nt++) {
                int col = cbase + nt * 8;
                float v0 = acc[mt][nt][2 * h], v1 = acc[mt][nt][2 * h + 1];
                if (mode) {
                    float gx = grow[col], gy = grow[col + 1];
                    float bx = bias[col], by = bias[col + 1];
                    v0 += fmaxf(gx + bx, 0.f);
                    v1 += fmaxf(gy + by, 0.f);
                }
                float2 o = make_float2(v0, v1);
                *(float2*)(crow + col) = o;
            }
        }
    }
}

// ---- row LayerNorm in place ----
__global__ __launch_bounds__(128) void k_ln(float* __restrict__ out,
                                            const float* __restrict__ gamma,
                                            const float* __restrict__ beta) {
    int n = blockIdx.x;
    int t = threadIdx.x;
    float4* row = (float4*)(out + (size_t)n * F);
    float4 v = row[t];
    float s = v.x + v.y + v.z + v.w;
    float q = v.x * v.x + v.y * v.y + v.z * v.z + v.w * v.w;
#pragma unroll
    for (int o = 16; o; o >>= 1) {
        s += __shfl_xor_sync(0xffffffffu, s, o);
        q += __shfl_xor_sync(0xffffffffu, q, o);
    }
    __shared__ float shs[4], shq[4];
    int w = t >> 5, l = t & 31;
    if (l == 0) { shs[w] = s; shq[w] = q; }
    __syncthreads();
    s = shs[0] + shs[1] + shs[2] + shs[3];
    q = shq[0] + shq[1] + shq[2] + shq[3];
    float mu = s * (1.f / F);
    float var = q * (1.f / F) - mu * mu;
    float inv = rsqrtf(var + LN_EPS);
    float4 gv = ((const float4*)gamma)[t];
    float4 bv = ((const float4*)beta)[t];
    v.x = (v.x - mu) * inv * gv.x + bv.x;
    v.y = (v.y - mu) * inv * gv.y + bv.y;
    v.z = (v.z - mu) * inv * gv.z + bv.z;
    v.w = (v.w - mu) * inv * gv.w + bv.w;
    row[t] = v;
}

extern "C" void kernel_launch(void* const* d_in, const int* in_sizes, int n_in,
                              void* d_out, int out_size) {
    const float* x = (const float*)d_in[0];
    const int* ei = (const int*)d_in[1];
    const float* ts = (const float*)d_in[2];
    const float* W_t = (const float*)d_in[3];
    const float* b_t = (const float*)d_in[4];
    const float* W_r = (const float*)d_in[5];
    const float* gamma = (const float*)d_in[6];
    const float* beta = (const float*)d_in[7];
    const void* gt = d_in[8];
    float* out = (float*)d_out;

    static int smem_set = 0;
    if (!smem_set) {
        cudaFuncSetAttribute(k_gemm_mma, cudaFuncAttributeMaxDynamicSharedMemorySize, SMEM_DYN);
        smem_set = 1;
    }

    k_init<<<(N_NODES + 255) / 256, 256>>>(gt);
    k_pass1<<<(N_EDGES + 255) / 256, 256>>>(ei, ts);
    k_weights<<<(N_EDGES + 255) / 256, 256>>>(ei, ts);
    k_dinv<<<(N_NODES + 255) / 256, 256>>>(gt);
    k_scan<<<1, 1024>>>();
    k_fill<<<(N_EDGES + 255) / 256, 256>>>(ei);

    for (int s = 0; s < 5; s++) k_spmm<<<N_NODES, 128>>>(s, x, gt);

    dim3 gg((N_NODES + TILE_M - 1) / TILE_M, F / TILE_N);
    k_gemm_mma<<<gg, 256, SMEM_DYN>>>(0, nullptr, W_t, nullptr, nullptr);
    k_gemm_mma<<<gg, 256, SMEM_DYN>>>(1, x, W_r, b_t, out);
    k_ln<<<N_NODES, 128>>>(out, gamma, beta);
}

// round 4
// speedup vs baseline: 1.9050x; 1.0804x over previous
#include <cuda_runtime.h>
#include <cuda_bf16.h>
#include <cstdint>

#define N_NODES 20000
#define N_EDGES 320000
#define F 512
#define F4 128
#define DT 0.2f
#define TDECAY 0.1f
#define LN_EPS 1e-5f

// ---- GEMM tiling (mma.sync bf16-split, pre-converted inputs) ----
#define TILE_M 128
#define TILE_N 128
#define KCHUNK 32
#define NCH1 16                      // chunks per GEMM phase (512/32)
#define ROWB 80                      // padded smem row stride in bytes (32 bf16 + 16 pad)
#define TSZ (128 * ROWB)             // 10240 bytes per tile
#define BUF_SZ (4 * TSZ)             // Ahi, Alo, Bhi, Blo = 40960
#define SMEM_DYN (2 * BUF_SZ)        // double buffered = 81920

// ---- static device scratch ----
__device__ float g_w[N_EDGES];
__device__ float g_degw[N_NODES];
__device__ float g_dinv[N_NODES];
__device__ int   g_cnt[N_NODES];
__device__ int   g_rowptr[N_NODES + 1];
__device__ int   g_cursor[N_NODES];
__device__ int   g_srcs[N_EDGES];
__device__ float g_ews[N_EDGES];
__device__ float g_ha[(size_t)N_NODES * F];
__device__ float g_hb[(size_t)N_NODES * F];
__device__ unsigned g_tmax_bits;
// bf16 hi/lo split operands
__device__ __nv_bfloat16 g_h_hi[(size_t)N_NODES * F];
__device__ __nv_bfloat16 g_h_lo[(size_t)N_NODES * F];
__device__ __nv_bfloat16 g_x_hi[(size_t)N_NODES * F];
__device__ __nv_bfloat16 g_x_lo[(size_t)N_NODES * F];
__device__ __nv_bfloat16 g_wt_hi[F * F];
__device__ __nv_bfloat16 g_wt_lo[F * F];
__device__ __nv_bfloat16 g_wr_hi[F * F];
__device__ __nv_bfloat16 g_wr_lo[F * F];

// ---------------- helpers ----------------
__device__ __forceinline__ uint32_t smem_u32(const void* p) {
    uint32_t a;
    asm("{ .reg .u64 t; cvta.to.shared.u64 t, %1; cvt.u32.u64 %0, t; }" : "=r"(a) : "l"(p));
    return a;
}
__device__ __forceinline__ void ldsm4(unsigned* r, uint32_t addr) {
    asm volatile("ldmatrix.sync.aligned.m8n8.x4.shared.b16 {%0,%1,%2,%3}, [%4];"
                 : "=r"(r[0]), "=r"(r[1]), "=r"(r[2]), "=r"(r[3]) : "r"(addr));
}
__device__ __forceinline__ void mma_bf16(float* d, const unsigned* a, unsigned b0, unsigned b1) {
    asm volatile(
        "mma.sync.aligned.m16n8k16.row.col.f32.bf16.bf16.f32 "
        "{%0,%1,%2,%3}, {%4,%5,%6,%7}, {%8,%9}, {%0,%1,%2,%3};"
        : "+f"(d[0]), "+f"(d[1]), "+f"(d[2]), "+f"(d[3])
        : "r"(a[0]), "r"(a[1]), "r"(a[2]), "r"(a[3]), "r"(b0), "r"(b1));
}
__device__ __forceinline__ void cpa16(uint32_t dst, const void* src, int src_sz) {
    asm volatile("cp.async.cg.shared.global [%0], [%1], 16, %2;"
                 :: "r"(dst), "l"(src), "r"(src_sz));
}
__device__ __forceinline__ void cpa_commit() {
    asm volatile("cp.async.commit_group;" ::: "memory");
}
__device__ __forceinline__ void cpa_wait0() {
    asm volatile("cp.async.wait_group 0;" ::: "memory");
}
__device__ __forceinline__ unsigned pack_bf16(float a, float b) {
    __nv_bfloat162 p = __floats2bfloat162_rn(a, b);
    return *reinterpret_cast<unsigned*>(&p);
}
// graph_time arrives as a scalar; robust to int32/int64/float32 encodings.
__device__ __forceinline__ float decode_gt(const void* p) {
    int iv = *(const int*)p;
    if (iv >= 0 && iv < (1 << 24)) return (float)iv;
    return *(const float*)p;
}

// ---- fp32 -> bf16 hi/lo conversion; which: 0=h(g_ha), 1=x, 2=W_t, 3=W_r ----
__global__ void k_conv(int which, const float* __restrict__ ext, int n4) {
    int i = blockIdx.x * blockDim.x + threadIdx.x;
    if (i >= n4) return;
    const float* src;
    __nv_bfloat16 *hi, *lo;
    if (which == 0)      { src = g_ha; hi = g_h_hi; lo = g_h_lo; }
    else if (which == 1) { src = ext;  hi = g_x_hi; lo = g_x_lo; }
    else if (which == 2) { src = ext;  hi = g_wt_hi; lo = g_wt_lo; }
    else                 { src = ext;  hi = g_wr_hi; lo = g_wr_lo; }
    float4 v = ((const float4*)src)[i];
    float hx = __bfloat162float(__float2bfloat16(v.x));
    float hy = __bfloat162float(__float2bfloat16(v.y));
    float hz = __bfloat162float(__float2bfloat16(v.z));
    float hw = __bfloat162float(__float2bfloat16(v.w));
    ((uint2*)hi)[i] = make_uint2(pack_bf16(v.x, v.y), pack_bf16(v.z, v.w));
    ((uint2*)lo)[i] = make_uint2(pack_bf16(v.x - hx, v.y - hy), pack_bf16(v.z - hz, v.w - hw));
}

// ---- preprocessing kernels ----
__global__ void k_init(const void* gt_ptr) {
    int i = blockIdx.x * blockDim.x + threadIdx.x;
    if (i < N_NODES) { g_cnt[i] = 0; g_degw[i] = 0.f; }
    if (i == 0) g_tmax_bits = __float_as_uint(decode_gt(gt_ptr));
}

__global__ void k_pass1(const int* __restrict__ ei, const float* __restrict__ ts) {
    int e = blockIdx.x * blockDim.x + threadIdx.x;   // grid covers exactly N_EDGES
    unsigned mb = __float_as_uint(ts[e]);            // ts >= 0 so uint order == float order
#pragma unroll
    for (int o = 16; o; o >>= 1) mb = max(mb, __shfl_xor_sync(0xffffffffu, mb, o));
    if ((threadIdx.x & 31) == 0) atomicMax(&g_tmax_bits, mb);
    atomicAdd(&g_cnt[ei[N_EDGES + e]], 1);
}

__global__ void k_weights(const int* __restrict__ ei, const float* __restrict__ ts) {
    int e = blockIdx.x * blockDim.x + threadIdx.x;
    if (e >= N_EDGES) return;
    float tmax = __uint_as_float(g_tmax_bits);
    float w = expf(-TDECAY * (tmax - ts[e]));
    g_w[e] = w;
    atomicAdd(&g_degw[ei[N_EDGES + e]], w);
}

__global__ void k_dinv(const void* gt_ptr) {
    int i = blockIdx.x * blockDim.x + threadIdx.x;
    if (i >= N_NODES) return;
    float tmax = __uint_as_float(g_tmax_bits);
    float self_w = expf(-TDECAY * (tmax - decode_gt(gt_ptr)));
    float tot = g_degw[i] + self_w;
    g_dinv[i] = (tot > 0.f) ? (1.f / sqrtf(tot)) : 0.f;
}

__global__ void k_scan() {
    __shared__ int sh[1024];
    int t = threadIdx.x;
    const int CH = 20;
    int beg = t * CH;
    int lsum = 0;
    for (int i = 0; i < CH; i++) {
        int idx = beg + i;
        if (idx < N_NODES) lsum += g_cnt[idx];
    }
    sh[t] = lsum;
    __syncthreads();
    for (int off = 1; off < 1024; off <<= 1) {
        int v = 0;
        if (t >= off) v = sh[t - off];
        __syncthreads();
        sh[t] += v;
        __syncthreads();
    }
    int run = sh[t] - lsum;
    for (int i = 0; i < CH; i++) {
        int idx = beg + i;
        if (idx < N_NODES) {
            g_rowptr[idx] = run;
            g_cursor[idx] = run;
            run += g_cnt[idx];
        }
    }
    if (t == 1023) g_rowptr[N_NODES] = sh[1023];
}

__global__ void k_fill(const int* __restrict__ ei) {
    int e = blockIdx.x * blockDim.x + threadIdx.x;
    if (e >= N_EDGES) return;
    int src = ei[e], dst = ei[N_EDGES + e];
    int p = atomicAdd(&g_cursor[dst], 1);
    g_srcs[p] = src;
    g_ews[p] = g_dinv[src] * g_w[e] * g_dinv[dst];
}

// ---- diffusion SpMM; last step emits bf16 hi/lo directly ----
__global__ __launch_bounds__(128) void k_spmm(int step, const float* __restrict__ x,
                                              const void* gt_ptr) {
    const float* hin = (step == 0) ? x : ((step & 1) ? g_ha : g_hb);
    float* hout = (step & 1) ? g_hb : g_ha;
    int n = blockIdx.x;
    int t = threadIdx.x;

    float tmax = __uint_as_float(g_tmax_bits);
    float self_w = expf(-TDECAY * (tmax - decode_gt(gt_ptr)));
    float dv = g_dinv[n];
    float coef = (1.f - DT) + DT * self_w * dv * dv;

    const float4* hin4 = (const float4*)hin;
    float4 hv = hin4[(size_t)n * F4 + t];
    float4 acc;
    acc.x = coef * hv.x; acc.y = coef * hv.y; acc.z = coef * hv.z; acc.w = coef * hv.w;

    int beg = g_rowptr[n], end = g_rowptr[n + 1];
    __shared__ int s_src[128];
    __shared__ float s_ew[128];
    for (int base = beg; base < end; base += 128) {
        int cnt = min(128, end - base);
        if (t < cnt) {
            s_src[t] = g_srcs[base + t];
            s_ew[t] = DT * g_ews[base + t];
        }
        __syncthreads();
        int j = 0;
        for (; j + 8 <= cnt; j += 8) {
            int si[8]; float w[8]; float4 v[8];
#pragma unroll
            for (int u = 0; u < 8; u++) { si[u] = s_src[j + u]; w[u] = s_ew[j + u]; }
#pragma unroll
            for (int u = 0; u < 8; u++) v[u] = hin4[(size_t)si[u] * F4 + t];
#pragma unroll
            for (int u = 0; u < 8; u++) {
                acc.x += w[u] * v[u].x; acc.y += w[u] * v[u].y;
                acc.z += w[u] * v[u].z; acc.w += w[u] * v[u].w;
            }
        }
        for (; j < cnt; j++) {
            float w = s_ew[j];
            float4 v = hin4[(size_t)s_src[j] * F4 + t];
            acc.x += w*v.x; acc.y += w*v.y; acc.z += w*v.z; acc.w += w*v.w;
        }
        __syncthreads();
    }
    if (step == 4) {
        // emit split bf16 directly (h is only consumed by the GEMM)
        float hx = __bfloat162float(__float2bfloat16(acc.x));
        float hy = __bfloat162float(__float2bfloat16(acc.y));
        float hz = __bfloat162float(__float2bfloat16(acc.z));
        float hw = __bfloat162float(__float2bfloat16(acc.w));
        size_t idx = (size_t)n * (F / 2) + 2 * t;   // uint index into bf16x2 arrays
        ((uint2*)g_h_hi)[idx >> 1] = make_uint2(pack_bf16(acc.x, acc.y), pack_bf16(acc.z, acc.w));
        ((uint2*)g_h_lo)[idx >> 1] = make_uint2(pack_bf16(acc.x - hx, acc.y - hy),
                                                pack_bf16(acc.z - hz, acc.w - hw));
    } else {
        ((float4*)hout)[(size_t)n * F4 + t] = acc;
    }
}

// ---- chunk loader: 4 bf16 tiles (Ahi,Alo,Bhi,Blo), 128 rows x 32 cols, cp.async ----
__device__ __forceinline__ void load_chunk(uint32_t sb,
                                           const __nv_bfloat16* __restrict__ Ah,
                                           const __nv_bfloat16* __restrict__ Al,
                                           const __nv_bfloat16* __restrict__ Bh,
                                           const __nv_bfloat16* __restrict__ Bl,
                                           int arow0, int brow0, int k0, int t) {
#pragma unroll
    for (int it = 0; it < 2; it++) {
        int s = t + it * 256;
        int row = s >> 2, q = s & 3;
        uint32_t doff = row * ROWB + q * 16;
        int ar = arow0 + row;
        int ok = (ar < N_NODES) ? 16 : 0;
        size_t aoff = (size_t)(ok ? ar : 0) * F + k0 + q * 8;
        size_t boff = (size_t)(brow0 + row) * F + k0 + q * 8;
        cpa16(sb + 0 * TSZ + doff, Ah + aoff, ok);
        cpa16(sb + 1 * TSZ + doff, Al + aoff, ok);
        cpa16(sb + 2 * TSZ + doff, Bh + boff, 16);
        cpa16(sb + 3 * TSZ + doff, Bl + boff, 16);
    }
}

// ---- fused dual GEMM: out = relu(h@Wt^T + b) + x@Wr^T  (split-bf16, 3-pass) ----
__global__ __launch_bounds__(256, 2) void k_gemm2(const float* __restrict__ bias,
                                                  float* __restrict__ out) {
    extern __shared__ char smd[];
    int t = threadIdx.x, lane = t & 31, wid = t >> 5;
    int wm = wid >> 1, wn = wid & 1;
    int bm = blockIdx.x, bn = blockIdx.y;

    int lr8 = lane & 7, lt = lane >> 3;
    int row_off = lr8 + (lt & 1) * 8;
    int col_off = (lt >> 1) * 8;

    float acc[2][8][4];
#pragma unroll
    for (int i = 0; i < 2; i++)
#pragma unroll
        for (int j = 0; j < 8; j++)
#pragma unroll
            for (int q = 0; q < 4; q++) acc[i][j][q] = 0.f;

    uint32_t sbase = smem_u32(smd);
    int am0 = bm * TILE_M, bn0 = bn * TILE_N;

    load_chunk(sbase, g_h_hi, g_h_lo, g_wt_hi, g_wt_lo, am0, bn0, 0, t);
    cpa_commit();

    for (int c = 0; c < 2 * NCH1; c++) {
        cpa_wait0();
        __syncthreads();
        if (c + 1 < 2 * NCH1) {
            int cn = c + 1;
            uint32_t nsb = sbase + (cn & 1) * BUF_SZ;
            if (cn < NCH1)
                load_chunk(nsb, g_h_hi, g_h_lo, g_wt_hi, g_wt_lo, am0, bn0, cn * KCHUNK, t);
            else
                load_chunk(nsb, g_x_hi, g_x_lo, g_wr_hi, g_wr_lo, am0, bn0,
                           (cn - NCH1) * KCHUNK, t);
            cpa_commit();
        }
        uint32_t sb = sbase + (c & 1) * BUF_SZ;
#pragma unroll
        for (int pass = 0; pass < 3; pass++) {
            uint32_t aBase = sb + ((pass == 2) ? TSZ : 0);
            uint32_t bBase = sb + 2 * TSZ + ((pass == 1) ? TSZ : 0);
#pragma unroll
            for (int ks = 0; ks < 2; ks++) {
                unsigned af[2][4];
#pragma unroll
                for (int mt = 0; mt < 2; mt++)
                    ldsm4(af[mt], aBase + (wm * 32 + mt * 16 + row_off) * ROWB
                                        + (ks * 16 + col_off) * 2);
                unsigned bf[4][4];
#pragma unroll
                for (int pr = 0; pr < 4; pr++)
                    ldsm4(bf[pr], bBase + (wn * 64 + pr * 16 + row_off) * ROWB
                                        + (ks * 16 + col_off) * 2);
#pragma unroll
                for (int mt = 0; mt < 2; mt++)
#pragma unroll
                    for (int nt = 0; nt < 8; nt++) {
                        int pr = nt >> 1, h = nt & 1;
                        mma_bf16(acc[mt][nt], af[mt], bf[pr][h], bf[pr][h + 2]);
                    }
            }
        }
        if (c == NCH1 - 1) {
            // acc = relu(acc + bias); then keep accumulating x@Wr^T into same regs
            int cb = bn0 + wn * 64 + 2 * (lane & 3);
#pragma unroll
            for (int nt = 0; nt < 8; nt++) {
                float b0 = __ldg(bias + cb + nt * 8);
                float b1 = __ldg(bias + cb + nt * 8 + 1);
#pragma unroll
                for (int mt = 0; mt < 2; mt++) {
                    acc[mt][nt][0] = fmaxf(acc[mt][nt][0] + b0, 0.f);
                    acc[mt][nt][1] = fmaxf(acc[mt][nt][1] + b1, 0.f);
                    acc[mt][nt][2] = fmaxf(acc[mt][nt][2] + b0, 0.f);
                    acc[mt][nt][3] = fmaxf(acc[mt][nt][3] + b1, 0.f);
                }
            }
        }
        __syncthreads();
    }

    int rbase = am0 + wm * 32 + (lane >> 2);
    int cbase = bn0 + wn * 64 + 2 * (lane & 3);
#pragma unroll
    for (int mt = 0; mt < 2; mt++) {
#pragma unroll
        for (int h = 0; h < 2; h++) {
            int row = rbase + mt * 16 + h * 8;
            if (row >= N_NODES) continue;
            float* crow = out + (size_t)row * F;
#pragma unroll
            for (int nt = 0; nt < 8; nt++) {
                int col = cbase + nt * 8;
                *(float2*)(crow + col) = make_float2(acc[mt][nt][2 * h], acc[mt][nt][2 * h + 1]);
            }
        }
    }
}

// ---- row LayerNorm in place ----
__global__ __launch_bounds__(128) void k_ln(float* __restrict__ out,
                                            const float* __restrict__ gamma,
                                            const float* __restrict__ beta) {
    int n = blockIdx.x;
    int t = threadIdx.x;
    float4* row = (float4*)(out + (size_t)n * F);
    float4 v = row[t];
    float s = v.x + v.y + v.z + v.w;
    float q = v.x * v.x + v.y * v.y + v.z * v.z + v.w * v.w;
#pragma unroll
    for (int o = 16; o; o >>= 1) {
        s += __shfl_xor_sync(0xffffffffu, s, o);
        q += __shfl_xor_sync(0xffffffffu, q, o);
    }
    __shared__ float shs[4], shq[4];
    int w = t >> 5, l = t & 31;
    if (l == 0) { shs[w] = s; shq[w] = q; }
    __syncthreads();
    s = shs[0] + shs[1] + shs[2] + shs[3];
    q = shq[0] + shq[1] + shq[2] + shq[3];
    float mu = s * (1.f / F);
    float var = q * (1.f / F) - mu * mu;
    float inv = rsqrtf(var + LN_EPS);
    float4 gv = ((const float4*)gamma)[t];
    float4 bv = ((const float4*)beta)[t];
    v.x = (v.x - mu) * inv * gv.x + bv.x;
    v.y = (v.y - mu) * inv * gv.y + bv.y;
    v.z = (v.z - mu) * inv * gv.z + bv.z;
    v.w = (v.w - mu) * inv * gv.w + bv.w;
    row[t] = v;
}

extern "C" void kernel_launch(void* const* d_in, const int* in_sizes, int n_in,
                              void* d_out, int out_size) {
    const float* x = (const float*)d_in[0];
    const int* ei = (const int*)d_in[1];
    const float* ts = (const float*)d_in[2];
    const float* W_t = (const float*)d_in[3];
    const float* b_t = (const float*)d_in[4];
    const float* W_r = (const float*)d_in[5];
    const float* gamma = (const float*)d_in[6];
    const float* beta = (const float*)d_in[7];
    const void* gt = d_in[8];
    float* out = (float*)d_out;

    cudaFuncSetAttribute(k_gemm2, cudaFuncAttributeMaxDynamicSharedMemorySize, SMEM_DYN);

    const int NF4 = N_NODES * F / 4;     // 2.56M
    const int WF4 = F * F / 4;           // 65536

    // input conversions (independent of graph preprocessing)
    k_conv<<<(NF4 + 255) / 256, 256>>>(1, x, NF4);
    k_conv<<<(WF4 + 255) / 256, 256>>>(2, W_t, WF4);
    k_conv<<<(WF4 + 255) / 256, 256>>>(3, W_r, WF4);

    k_init<<<(N_NODES + 255) / 256, 256>>>(gt);
    k_pass1<<<N_EDGES / 256, 256>>>(ei, ts);
    k_weights<<<N_EDGES / 256, 256>>>(ei, ts);
    k_dinv<<<(N_NODES + 255) / 256, 256>>>(gt);
    k_scan<<<1, 1024>>>();
    k_fill<<<N_EDGES / 256, 256>>>(ei);

    for (int s = 0; s < 5; s++) k_spmm<<<N_NODES, 128>>>(s, x, gt);

    dim3 gg((N_NODES + TILE_M - 1) / TILE_M, F / TILE_N);
    k_gemm2<<<gg, 256, SMEM_DYN>>>(b_t, out);
    k_ln<<<N_NODES, 128>>>(out, gamma, beta);
}

// round 5
// speedup vs baseline: 2.0961x; 1.1003x over previous
#include <cuda_runtime.h>
#include <cuda_bf16.h>
#include <cuda_fp16.h>
#include <cstdint>

#define N_NODES 20000
#define N_EDGES 320000
#define F 512
#define DT 0.2f
#define TDECAY 0.1f
#define LN_EPS 1e-5f

// ---- GEMM tiling (mma.sync bf16-split, pre-converted inputs) ----
#define TILE_M 128
#define TILE_N 128
#define KCHUNK 32
#define NCH1 16
#define ROWB 80
#define TSZ (128 * ROWB)
#define BUF_SZ (4 * TSZ)
#define SMEM_DYN (2 * BUF_SZ)   // 81920

// ---- static device scratch ----
__device__ float g_w[N_EDGES];
__device__ float g_degw[N_NODES];
__device__ float g_dinv[N_NODES];
__device__ int   g_cnt[N_NODES];
__device__ int   g_rowptr[N_NODES + 1];
__device__ int   g_cursor[N_NODES];
__device__ int   g_srcs[N_EDGES];
__device__ float g_ews[N_EDGES];
__device__ unsigned g_tmax_bits;
// fp16 diffusion state (ping/pong) + fp16 x
__device__ uint2 g_f16a[(size_t)N_NODES * F / 4];
__device__ uint2 g_f16b[(size_t)N_NODES * F / 4];
__device__ uint2 g_xf16[(size_t)N_NODES * F / 4];
// bf16 hi/lo split operands for the GEMM
__device__ __nv_bfloat16 g_h_hi[(size_t)N_NODES * F];
__device__ __nv_bfloat16 g_h_lo[(size_t)N_NODES * F];
__device__ __nv_bfloat16 g_x_hi[(size_t)N_NODES * F];
__device__ __nv_bfloat16 g_x_lo[(size_t)N_NODES * F];
__device__ __nv_bfloat16 g_wt_hi[F * F];
__device__ __nv_bfloat16 g_wt_lo[F * F];
__device__ __nv_bfloat16 g_wr_hi[F * F];
__device__ __nv_bfloat16 g_wr_lo[F * F];

// ---------------- helpers ----------------
__device__ __forceinline__ uint32_t smem_u32(const void* p) {
    uint32_t a;
    asm("{ .reg .u64 t; cvta.to.shared.u64 t, %1; cvt.u32.u64 %0, t; }" : "=r"(a) : "l"(p));
    return a;
}
__device__ __forceinline__ void ldsm4(unsigned* r, uint32_t addr) {
    asm volatile("ldmatrix.sync.aligned.m8n8.x4.shared.b16 {%0,%1,%2,%3}, [%4];"
                 : "=r"(r[0]), "=r"(r[1]), "=r"(r[2]), "=r"(r[3]) : "r"(addr));
}
__device__ __forceinline__ void mma_bf16(float* d, const unsigned* a, unsigned b0, unsigned b1) {
    asm volatile(
        "mma.sync.aligned.m16n8k16.row.col.f32.bf16.bf16.f32 "
        "{%0,%1,%2,%3}, {%4,%5,%6,%7}, {%8,%9}, {%0,%1,%2,%3};"
        : "+f"(d[0]), "+f"(d[1]), "+f"(d[2]), "+f"(d[3])
        : "r"(a[0]), "r"(a[1]), "r"(a[2]), "r"(a[3]), "r"(b0), "r"(b1));
}
__device__ __forceinline__ void cpa16(uint32_t dst, const void* src, int src_sz) {
    asm volatile("cp.async.cg.shared.global [%0], [%1], 16, %2;"
                 :: "r"(dst), "l"(src), "r"(src_sz));
}
__device__ __forceinline__ void cpa_commit() {
    asm volatile("cp.async.commit_group;" ::: "memory");
}
__device__ __forceinline__ void cpa_wait0() {
    asm volatile("cp.async.wait_group 0;" ::: "memory");
}
__device__ __forceinline__ unsigned pack_bf16(float a, float b) {
    __nv_bfloat162 p = __floats2bfloat162_rn(a, b);
    return *reinterpret_cast<unsigned*>(&p);
}
__device__ __forceinline__ unsigned pack_f16(float a, float b) {
    __half2 p = __float22half2_rn(make_float2(a, b));
    return *reinterpret_cast<unsigned*>(&p);
}
// graph_time arrives as a scalar; robust to int32/int64/float32 encodings.
__device__ __forceinline__ float decode_gt(const void* p) {
    int iv = *(const int*)p;
    if (iv >= 0 && iv < (1 << 24)) return (float)iv;
    return *(const float*)p;
}

// ---- fp32 -> bf16 hi/lo (+ fp16 for x); which: 1=x, 2=W_t, 3=W_r ----
__global__ void k_conv(int which, const float* __restrict__ ext, int n4) {
    int i = blockIdx.x * blockDim.x + threadIdx.x;
    if (i >= n4) return;
    __nv_bfloat16 *hi, *lo;
    if (which == 1)      { hi = g_x_hi; lo = g_x_lo; }
    else if (which == 2) { hi = g_wt_hi; lo = g_wt_lo; }
    else                 { hi = g_wr_hi; lo = g_wr_lo; }
    float4 v = ((const float4*)ext)[i];
    float hx = __bfloat162float(__float2bfloat16(v.x));
    float hy = __bfloat162float(__float2bfloat16(v.y));
    float hz = __bfloat162float(__float2bfloat16(v.z));
    float hw = __bfloat162float(__float2bfloat16(v.w));
    ((uint2*)hi)[i] = make_uint2(pack_bf16(v.x, v.y), pack_bf16(v.z, v.w));
    ((uint2*)lo)[i] = make_uint2(pack_bf16(v.x - hx, v.y - hy), pack_bf16(v.z - hz, v.w - hw));
    if (which == 1)
        g_xf16[i] = make_uint2(pack_f16(v.x, v.y), pack_f16(v.z, v.w));
}

// ---- preprocessing kernels ----
__global__ void k_init(const void* gt_ptr) {
    int i = blockIdx.x * blockDim.x + threadIdx.x;
    if (i < N_NODES) { g_cnt[i] = 0; g_degw[i] = 0.f; }
    if (i == 0) g_tmax_bits = __float_as_uint(decode_gt(gt_ptr));
}

__global__ void k_pass1(const int* __restrict__ ei, const float* __restrict__ ts) {
    int e = blockIdx.x * blockDim.x + threadIdx.x;   // grid covers exactly N_EDGES
    unsigned mb = __float_as_uint(ts[e]);            // ts >= 0 so uint order == float order
#pragma unroll
    for (int o = 16; o; o >>= 1) mb = max(mb, __shfl_xor_sync(0xffffffffu, mb, o));
    if ((threadIdx.x & 31) == 0) atomicMax(&g_tmax_bits, mb);
    atomicAdd(&g_cnt[ei[N_EDGES + e]], 1);
}

__global__ void k_weights(const int* __restrict__ ei, const float* __restrict__ ts) {
    int e = blockIdx.x * blockDim.x + threadIdx.x;
    if (e >= N_EDGES) return;
    float tmax = __uint_as_float(g_tmax_bits);
    float w = expf(-TDECAY * (tmax - ts[e]));
    g_w[e] = w;
    atomicAdd(&g_degw[ei[N_EDGES + e]], w);
}

__global__ void k_dinv(const void* gt_ptr) {
    int i = blockIdx.x * blockDim.x + threadIdx.x;
    if (i >= N_NODES) return;
    float tmax = __uint_as_float(g_tmax_bits);
    float self_w = expf(-TDECAY * (tmax - decode_gt(gt_ptr)));
    float tot = g_degw[i] + self_w;
    g_dinv[i] = (tot > 0.f) ? (1.f / sqrtf(tot)) : 0.f;
}

__global__ void k_scan() {
    __shared__ int sh[1024];
    int t = threadIdx.x;
    const int CH = 20;
    int beg = t * CH;
    int lsum = 0;
    for (int i = 0; i < CH; i++) {
        int idx = beg + i;
        if (idx < N_NODES) lsum += g_cnt[idx];
    }
    sh[t] = lsum;
    __syncthreads();
    for (int off = 1; off < 1024; off <<= 1) {
        int v = 0;
        if (t >= off) v = sh[t - off];
        __syncthreads();
        sh[t] += v;
        __syncthreads();
    }
    int run = sh[t] - lsum;
    for (int i = 0; i < CH; i++) {
        int idx = beg + i;
        if (idx < N_NODES) {
            g_rowptr[idx] = run;
            g_cursor[idx] = run;
            run += g_cnt[idx];
        }
    }
    if (t == 1023) g_rowptr[N_NODES] = sh[1023];
}

__global__ void k_fill(const int* __restrict__ ei) {
    int e = blockIdx.x * blockDim.x + threadIdx.x;
    if (e >= N_EDGES) return;
    int src = ei[e], dst = ei[N_EDGES + e];
    int p = atomicAdd(&g_cursor[dst], 1);
    g_srcs[p] = src;
    g_ews[p] = g_dinv[src] * g_w[e] * g_dinv[dst];
}

// ---- fp16 diffusion SpMM: thread t covers 4 features (uint2 = 4 halfs) ----
// in:  step0 -> xf16, else ping/pong.  out: steps 0-3 fp16; step 4 bf16 hi/lo split.
__global__ __launch_bounds__(128) void k_spmm16(int step, const void* gt_ptr) {
    const uint2* hin = (step == 0) ? g_xf16 : ((step & 1) ? g_f16a : g_f16b);
    uint2* hout = (step & 1) ? g_f16b : g_f16a;
    int n = blockIdx.x;
    int t = threadIdx.x;

    float tmax = __uint_as_float(g_tmax_bits);
    float self_w = expf(-TDECAY * (tmax - decode_gt(gt_ptr)));
    float dv = g_dinv[n];
    float coef = (1.f - DT) + DT * self_w * dv * dv;

    size_t self_idx = (size_t)n * 128 + t;
    uint2 su = hin[self_idx];
    float2 s0 = __half22float2(*reinterpret_cast<__half2*>(&su.x));
    float2 s1 = __half22float2(*reinterpret_cast<__half2*>(&su.y));
    float4 acc = make_float4(coef * s0.x, coef * s0.y, coef * s1.x, coef * s1.y);

    int beg = g_rowptr[n], end = g_rowptr[n + 1];
    __shared__ int s_src[128];
    __shared__ float s_ew[128];
    for (int base = beg; base < end; base += 128) {
        int cnt = min(128, end - base);
        if (t < cnt) {
            s_src[t] = g_srcs[base + t];
            s_ew[t] = DT * g_ews[base + t];
        }
        __syncthreads();
        int j = 0;
        for (; j + 8 <= cnt; j += 8) {
            int si[8]; float w[8]; uint2 u[8];
#pragma unroll
            for (int q = 0; q < 8; q++) { si[q] = s_src[j + q]; w[q] = s_ew[j + q]; }
#pragma unroll
            for (int q = 0; q < 8; q++) u[q] = hin[(size_t)si[q] * 128 + t];
#pragma unroll
            for (int q = 0; q < 8; q++) {
                float2 f0 = __half22float2(*reinterpret_cast<__half2*>(&u[q].x));
                float2 f1 = __half22float2(*reinterpret_cast<__half2*>(&u[q].y));
                acc.x += w[q] * f0.x; acc.y += w[q] * f0.y;
                acc.z += w[q] * f1.x; acc.w += w[q] * f1.y;
            }
        }
        for (; j < cnt; j++) {
            float w = s_ew[j];
            uint2 u = hin[(size_t)s_src[j] * 128 + t];
            float2 f0 = __half22float2(*reinterpret_cast<__half2*>(&u.x));
            float2 f1 = __half22float2(*reinterpret_cast<__half2*>(&u.y));
            acc.x += w * f0.x; acc.y += w * f0.y;
            acc.z += w * f1.x; acc.w += w * f1.y;
        }
        __syncthreads();
    }
    if (step == 4) {
        float hx = __bfloat162float(__float2bfloat16(acc.x));
        float hy = __bfloat162float(__float2bfloat16(acc.y));
        float hz = __bfloat162float(__float2bfloat16(acc.z));
        float hw = __bfloat162float(__float2bfloat16(acc.w));
        ((uint2*)g_h_hi)[self_idx] = make_uint2(pack_bf16(acc.x, acc.y), pack_bf16(acc.z, acc.w));
        ((uint2*)g_h_lo)[self_idx] = make_uint2(pack_bf16(acc.x - hx, acc.y - hy),
                                                pack_bf16(acc.z - hz, acc.w - hw));
    } else {
        hout[self_idx] = make_uint2(pack_f16(acc.x, acc.y), pack_f16(acc.z, acc.w));
    }
}

// ---- chunk loader: 4 bf16 tiles (Ahi,Alo,Bhi,Blo), 128 rows x 32 cols, cp.async ----
__device__ __forceinline__ void load_chunk(uint32_t sb,
                                           const __nv_bfloat16* __restrict__ Ah,
                                           const __nv_bfloat16* __restrict__ Al,
                                           const __nv_bfloat16* __restrict__ Bh,
                                           const __nv_bfloat16* __restrict__ Bl,
                                           int arow0, int brow0, int k0, int t) {
#pragma unroll
    for (int it = 0; it < 2; it++) {
        int s = t + it * 256;
        int row = s >> 2, q = s & 3;
        uint32_t doff = row * ROWB + q * 16;
        int ar = arow0 + row;
        int ok = (ar < N_NODES) ? 16 : 0;
        size_t aoff = (size_t)(ok ? ar : 0) * F + k0 + q * 8;
        size_t boff = (size_t)(brow0 + row) * F + k0 + q * 8;
        cpa16(sb + 0 * TSZ + doff, Ah + aoff, ok);
        cpa16(sb + 1 * TSZ + doff, Al + aoff, ok);
        cpa16(sb + 2 * TSZ + doff, Bh + boff, 16);
        cpa16(sb + 3 * TSZ + doff, Bl + boff, 16);
    }
}

// ---- fused dual GEMM: out = relu(h@Wt^T + b) + x@Wr^T  (split-bf16, 3-pass) ----
__global__ __launch_bounds__(256, 2) void k_gemm2(const float* __restrict__ bias,
                                                  float* __restrict__ out) {
    extern __shared__ char smd[];
    int t = threadIdx.x, lane = t & 31, wid = t >> 5;
    int wm = wid >> 1, wn = wid & 1;
    int bm = blockIdx.x, bn = blockIdx.y;

    int lr8 = lane & 7, lt = lane >> 3;
    int row_off = lr8 + (lt & 1) * 8;
    int col_off = (lt >> 1) * 8;

    float acc[2][8][4];
#pragma unroll
    for (int i = 0; i < 2; i++)
#pragma unroll
        for (int j = 0; j < 8; j++)
#pragma unroll
            for (int q = 0; q < 4; q++) acc[i][j][q] = 0.f;

    uint32_t sbase = smem_u32(smd);
    int am0 = bm * TILE_M, bn0 = bn * TILE_N;

    load_chunk(sbase, g_h_hi, g_h_lo, g_wt_hi, g_wt_lo, am0, bn0, 0, t);
    cpa_commit();

    for (int c = 0; c < 2 * NCH1; c++) {
        cpa_wait0();
        __syncthreads();
        if (c + 1 < 2 * NCH1) {
            int cn = c + 1;
            uint32_t nsb = sbase + (cn & 1) * BUF_SZ;
            if (cn < NCH1)
                load_chunk(nsb, g_h_hi, g_h_lo, g_wt_hi, g_wt_lo, am0, bn0, cn * KCHUNK, t);
            else
                load_chunk(nsb, g_x_hi, g_x_lo, g_wr_hi, g_wr_lo, am0, bn0,
                           (cn - NCH1) * KCHUNK, t);
            cpa_commit();
        }
        uint32_t sb = sbase + (c & 1) * BUF_SZ;
#pragma unroll
        for (int pass = 0; pass < 3; pass++) {
            uint32_t aBase = sb + ((pass == 2) ? TSZ : 0);
            uint32_t bBase = sb + 2 * TSZ + ((pass == 1) ? TSZ : 0);
#pragma unroll
            for (int ks = 0; ks < 2; ks++) {
                unsigned af[2][4];
#pragma unroll
                for (int mt = 0; mt < 2; mt++)
                    ldsm4(af[mt], aBase + (wm * 32 + mt * 16 + row_off) * ROWB
                                        + (ks * 16 + col_off) * 2);
                unsigned bf[4][4];
#pragma unroll
                for (int pr = 0; pr < 4; pr++)
                    ldsm4(bf[pr], bBase + (wn * 64 + pr * 16 + row_off) * ROWB
                                        + (ks * 16 + col_off) * 2);
#pragma unroll
                for (int mt = 0; mt < 2; mt++)
#pragma unroll
                    for (int nt = 0; nt < 8; nt++) {
                        int pr = nt >> 1, h = nt & 1;
                        mma_bf16(acc[mt][nt], af[mt], bf[pr][h], bf[pr][h + 2]);
                    }
            }
        }
        if (c == NCH1 - 1) {
            int cb = bn0 + wn * 64 + 2 * (lane & 3);
#pragma unroll
            for (int nt = 0; nt < 8; nt++) {
                float b0 = __ldg(bias + cb + nt * 8);
                float b1 = __ldg(bias + cb + nt * 8 + 1);
#pragma unroll
                for (int mt = 0; mt < 2; mt++) {
                    acc[mt][nt][0] = fmaxf(acc[mt][nt][0] + b0, 0.f);
                    acc[mt][nt][1] = fmaxf(acc[mt][nt][1] + b1, 0.f);
                    acc[mt][nt][2] = fmaxf(acc[mt][nt][2] + b0, 0.f);
                    acc[mt][nt][3] = fmaxf(acc[mt][nt][3] + b1, 0.f);
                }
            }
        }
        __syncthreads();
    }

    int rbase = am0 + wm * 32 + (lane >> 2);
    int cbase = bn0 + wn * 64 + 2 * (lane & 3);
#pragma unroll
    for (int mt = 0; mt < 2; mt++) {
#pragma unroll
        for (int h = 0; h < 2; h++) {
            int row = rbase + mt * 16 + h * 8;
            if (row >= N_NODES) continue;
            float* crow = out + (size_t)row * F;
#pragma unroll
            for (int nt = 0; nt < 8; nt++) {
                int col = cbase + nt * 8;
                *(float2*)(crow + col) = make_float2(acc[mt][nt][2 * h], acc[mt][nt][2 * h + 1]);
            }
        }
    }
}

// ---- row LayerNorm in place ----
__global__ __launch_bounds__(128) void k_ln(float* __restrict__ out,
                                            const float* __restrict__ gamma,
                                            const float* __restrict__ beta) {
    int n = blockIdx.x;
    int t = threadIdx.x;
    float4* row = (float4*)(out + (size_t)n * F);
    float4 v = row[t];
    float s = v.x + v.y + v.z + v.w;
    float q = v.x * v.x + v.y * v.y + v.z * v.z + v.w * v.w;
#pragma unroll
    for (int o = 16; o; o >>= 1) {
        s += __shfl_xor_sync(0xffffffffu, s, o);
        q += __shfl_xor_sync(0xffffffffu, q, o);
    }
    __shared__ float shs[4], shq[4];
    int w = t >> 5, l = t & 31;
    if (l == 0) { shs[w] = s; shq[w] = q; }
    __syncthreads();
    s = shs[0] + shs[1] + shs[2] + shs[3];
    q = shq[0] + shq[1] + shq[2] + shq[3];
    float mu = s * (1.f / F);
    float var = q * (1.f / F) - mu * mu;
    float inv = rsqrtf(var + LN_EPS);
    float4 gv = ((const float4*)gamma)[t];
    float4 bv = ((const float4*)beta)[t];
    v.x = (v.x - mu) * inv * gv.x + bv.x;
    v.y = (v.y - mu) * inv * gv.y + bv.y;
    v.z = (v.z - mu) * inv * gv.z + bv.z;
    v.w = (v.w - mu) * inv * gv.w + bv.w;
    row[t] = v;
}

extern "C" void kernel_launch(void* const* d_in, const int* in_sizes, int n_in,
                              void* d_out, int out_size) {
    const float* x = (const float*)d_in[0];
    const int* ei = (const int*)d_in[1];
    const float* ts = (const float*)d_in[2];
    const float* W_t = (const float*)d_in[3];
    const float* b_t = (const float*)d_in[4];
    const float* W_r = (const float*)d_in[5];
    const float* gamma = (const float*)d_in[6];
    const float* beta = (const float*)d_in[7];
    const void* gt = d_in[8];
    float* out = (float*)d_out;

    cudaFuncSetAttribute(k_gemm2, cudaFuncAttributeMaxDynamicSharedMemorySize, SMEM_DYN);

    const int NF4 = N_NODES * F / 4;
    const int WF4 = F * F / 4;

    k_conv<<<(NF4 + 255) / 256, 256>>>(1, x, NF4);
    k_conv<<<(WF4 + 255) / 256, 256>>>(2, W_t, WF4);
    k_conv<<<(WF4 + 255) / 256, 256>>>(3, W_r, WF4);

    k_init<<<(N_NODES + 255) / 256, 256>>>(gt);
    k_pass1<<<N_EDGES / 256, 256>>>(ei, ts);
    k_weights<<<N_EDGES / 256, 256>>>(ei, ts);
    k_dinv<<<(N_NODES + 255) / 256, 256>>>(gt);
    k_scan<<<1, 1024>>>();
    k_fill<<<N_EDGES / 256, 256>>>(ei);

    for (int s = 0; s < 5; s++) k_spmm16<<<N_NODES, 128>>>(s, gt);

    dim3 gg((N_NODES + TILE_M - 1) / TILE_M, F / TILE_N);
    k_gemm2<<<gg, 256, SMEM_DYN>>>(b_t, out);
    k_ln<<<N_NODES, 128>>>(out, gamma, beta);
}

// round 7
// speedup vs baseline: 2.1647x; 1.0327x over previous
#include <cuda_runtime.h>
#include <cuda_bf16.h>
#include <cuda_fp16.h>
#include <cstdint>

#define N_NODES 20000
#define N_EDGES 320000
#define F 512
#define DT 0.2f
#define TDECAY 0.1f
#define LN_EPS 1e-5f

// ---- GEMM tiling ----
#define TILE_M 128
#define TILE_N 128
#define KCHUNK 32
#define NCH1 16
#define ROWB 80
#define TSZ (128 * ROWB)
#define BUF_SZ (4 * TSZ)
#define SMEM_DYN (2 * BUF_SZ)   // 81920

#define NF8 (N_NODES * F / 8)   // 1,280,000 uint4 slots per node-feature array
#define WF8 (F * F / 8)         // 32768

// ---- static device scratch ----
__device__ float g_w[N_EDGES];          // exp(+c*ts), unscaled
__device__ float g_degw[N_NODES];       // sum of exp(+c*ts) into dst
__device__ float g_dinv[N_NODES];
__device__ int   g_cnt[N_NODES];
__device__ int   g_rowptr[N_NODES + 1];
__device__ int   g_cursor[N_NODES];
__device__ int2  g_edge[N_EDGES];       // {src, DT*ew as float bits}
__device__ unsigned g_tmax_bits;
// fp16 state (8 halfs per uint4)
__device__ uint4 g_xf16[NF8];
__device__ uint4 g_f16a[NF8];
__device__ uint4 g_f16b[NF8];
// bf16 hi/lo split operands (8 bf16 per uint4)
__device__ uint4 g_h_hi4[NF8];
__device__ uint4 g_h_lo4[NF8];
__device__ uint4 g_x_hi4[NF8];
__device__ uint4 g_x_lo4[NF8];
__device__ uint4 g_wt_hi4[WF8];
__device__ uint4 g_wt_lo4[WF8];
__device__ uint4 g_wr_hi4[WF8];
__device__ uint4 g_wr_lo4[WF8];

// ---------------- helpers ----------------
__device__ __forceinline__ uint32_t smem_u32(const void* p) {
    uint32_t a;
    asm("{ .reg .u64 t; cvta.to.shared.u64 t, %1; cvt.u32.u64 %0, t; }" : "=r"(a) : "l"(p));
    return a;
}
__device__ __forceinline__ void ldsm4(unsigned* r, uint32_t addr) {
    asm volatile("ldmatrix.sync.aligned.m8n8.x4.shared.b16 {%0,%1,%2,%3}, [%4];"
                 : "=r"(r[0]), "=r"(r[1]), "=r"(r[2]), "=r"(r[3]) : "r"(addr));
}
__device__ __forceinline__ void mma_bf16(float* d, const unsigned* a, unsigned b0, unsigned b1) {
    asm volatile(
        "mma.sync.aligned.m16n8k16.row.col.f32.bf16.bf16.f32 "
        "{%0,%1,%2,%3}, {%4,%5,%6,%7}, {%8,%9}, {%0,%1,%2,%3};"
        : "+f"(d[0]), "+f"(d[1]), "+f"(d[2]), "+f"(d[3])
        : "r"(a[0]), "r"(a[1]), "r"(a[2]), "r"(a[3]), "r"(b0), "r"(b1));
}
__device__ __forceinline__ void cpa16(uint32_t dst, const void* src, int src_sz) {
    asm volatile("cp.async.cg.shared.global [%0], [%1], 16, %2;"
                 :: "r"(dst), "l"(src), "r"(src_sz));
}
__device__ __forceinline__ void cpa_commit() {
    asm volatile("cp.async.commit_group;" ::: "memory");
}
__device__ __forceinline__ void cpa_wait0() {
    asm volatile("cp.async.wait_group 0;" ::: "memory");
}
__device__ __forceinline__ unsigned pack_bf16(float a, float b) {
    __nv_bfloat162 p = __floats2bfloat162_rn(a, b);
    return *reinterpret_cast<unsigned*>(&p);
}
__device__ __forceinline__ unsigned pack_f16(float a, float b) {
    __half2 p = __float22half2_rn(make_float2(a, b));
    return *reinterpret_cast<unsigned*>(&p);
}
__device__ __forceinline__ float decode_gt(const void* p) {
    int iv = *(const int*)p;
    if (iv >= 0 && iv < (1 << 24)) return (float)iv;
    return *(const float*)p;
}
__device__ __forceinline__ void accum8(float* acc, uint4 u, float w) {
    float2 f;
    f = __half22float2(*reinterpret_cast<__half2*>(&u.x)); acc[0] += w * f.x; acc[1] += w * f.y;
    f = __half22float2(*reinterpret_cast<__half2*>(&u.y)); acc[2] += w * f.x; acc[3] += w * f.y;
    f = __half22float2(*reinterpret_cast<__half2*>(&u.z)); acc[4] += w * f.x; acc[5] += w * f.y;
    f = __half22float2(*reinterpret_cast<__half2*>(&u.w)); acc[6] += w * f.x; acc[7] += w * f.y;
}

// ---- launch 0: init counters + convert x -> fp16 and bf16 hi/lo ----
__global__ void k_initconv(const float* __restrict__ x, const void* gt_ptr) {
    int i = blockIdx.x * blockDim.x + threadIdx.x;
    if (i < N_NODES) { g_cnt[i] = 0; g_degw[i] = 0.f; }
    if (i == 0) g_tmax_bits = __float_as_uint(decode_gt(gt_ptr));  // ts >= 0: uint order ok
    if (i >= NF8) return;
    float4 v0 = ((const float4*)x)[2 * i];
    float4 v1 = ((const float4*)x)[2 * i + 1];
    float f[8] = {v0.x, v0.y, v0.z, v0.w, v1.x, v1.y, v1.z, v1.w};
    uint4 h16, bhi, blo;
    unsigned* h = &h16.x; unsigned* hb = &bhi.x; unsigned* lb = &blo.x;
#pragma unroll
    for (int q = 0; q < 4; q++) {
        float a = f[2 * q], b = f[2 * q + 1];
        float ah = __bfloat162float(__float2bfloat16(a));
        float bh = __bfloat162float(__float2bfloat16(b));
        h[q] = pack_f16(a, b);
        hb[q] = pack_bf16(a, b);
        lb[q] = pack_bf16(a - ah, b - bh);
    }
    g_xf16[i] = h16;
    g_x_hi4[i] = bhi;
    g_x_lo4[i] = blo;
}

// ---- launch 1: edge pass (tmax, counts, unscaled degree, unscaled w) ----
__global__ void k_pass1w(const int* __restrict__ ei, const float* __restrict__ ts) {
    int e = blockIdx.x * blockDim.x + threadIdx.x;   // grid covers exactly N_EDGES
    float tse = ts[e];
    unsigned mb = __float_as_uint(tse);
#pragma unroll
    for (int o = 16; o; o >>= 1) mb = max(mb, __shfl_xor_sync(0xffffffffu, mb, o));
    if ((threadIdx.x & 31) == 0) atomicMax(&g_tmax_bits, mb);
    float u = expf(TDECAY * tse);        // w = u * exp(-c*tmax), scale applied later
    g_w[e] = u;
    int dst = ei[N_EDGES + e];
    atomicAdd(&g_cnt[dst], 1);
    atomicAdd(&g_degw[dst], u);
}

// ---- launch 2 ----
__global__ void k_dinv(const void* gt_ptr) {
    int i = blockIdx.x * blockDim.x + threadIdx.x;
    if (i >= N_NODES) return;
    float tmax = __uint_as_float(g_tmax_bits);
    float sc = expf(-TDECAY * tmax);
    float self_w = expf(-TDECAY * (tmax - decode_gt(gt_ptr)));
    float tot = g_degw[i] * sc + self_w;
    g_dinv[i] = (tot > 0.f) ? (1.f / sqrtf(tot)) : 0.f;
}

// ---- launch 3 ----
__global__ void k_scan() {
    __shared__ int sh[1024];
    int t = threadIdx.x;
    const int CH = 20;
    int beg = t * CH;
    int lsum = 0;
    for (int i = 0; i < CH; i++) {
        int idx = beg + i;
        if (idx < N_NODES) lsum += g_cnt[idx];
    }
    sh[t] = lsum;
    __syncthreads();
    for (int off = 1; off < 1024; off <<= 1) {
        int v = 0;
        if (t >= off) v = sh[t - off];
        __syncthreads();
        sh[t] += v;
        __syncthreads();
    }
    int run = sh[t] - lsum;
    for (int i = 0; i < CH; i++) {
        int idx = beg + i;
        if (idx < N_NODES) {
            g_rowptr[idx] = run;
            g_cursor[idx] = run;
            run += g_cnt[idx];
        }
    }
    if (t == 1023) g_rowptr[N_NODES] = sh[1023];
}

// ---- launch 4: CSR fill with fused weights (includes DT and tmax scaling) ----
__global__ void k_fill(const int* __restrict__ ei) {
    int e = blockIdx.x * blockDim.x + threadIdx.x;
    if (e >= N_EDGES) return;
    float tmax = __uint_as_float(g_tmax_bits);
    float sc = DT * expf(-TDECAY * tmax);
    int src = ei[e], dst = ei[N_EDGES + e];
    int p = atomicAdd(&g_cursor[dst], 1);
    float ew = g_dinv[src] * g_w[e] * sc * g_dinv[dst];
    g_edge[p] = make_int2(src, __float_as_int(ew));
}

// ---- launches 5-9: fp16 diffusion SpMM, 64 threads/node, uint4 gathers, no smem ----
__global__ __launch_bounds__(64) void k_spmm16(int step, const void* gt_ptr) {
    const uint4* __restrict__ hin = (step == 0) ? g_xf16 : ((step & 1) ? g_f16a : g_f16b);
    uint4* hout = (step & 1) ? g_f16b : g_f16a;
    int n = blockIdx.x, t = threadIdx.x;

    float tmax = __uint_as_float(g_tmax_bits);
    float self_w = expf(-TDECAY * (tmax - decode_gt(gt_ptr)));
    float dv = g_dinv[n];
    float coef = (1.f - DT) + DT * self_w * dv * dv;

    size_t self_idx = (size_t)n * 64 + t;
    float acc[8];
    {
        uint4 su = hin[self_idx];
        float2 f;
        f = __half22float2(*reinterpret_cast<__half2*>(&su.x)); acc[0] = coef * f.x; acc[1] = coef * f.y;
        f = __half22float2(*reinterpret_cast<__half2*>(&su.y)); acc[2] = coef * f.x; acc[3] = coef * f.y;
        f = __half22float2(*reinterpret_cast<__half2*>(&su.z)); acc[4] = coef * f.x; acc[5] = coef * f.y;
        f = __half22float2(*reinterpret_cast<__half2*>(&su.w)); acc[6] = coef * f.x; acc[7] = coef * f.y;
    }

    int j = g_rowptr[n], end = g_rowptr[n + 1];
    for (; j + 4 <= end; j += 4) {
        int2 e0 = g_edge[j], e1 = g_edge[j + 1], e2 = g_edge[j + 2], e3 = g_edge[j + 3];
        uint4 u0 = hin[(size_t)e0.x * 64 + t];
        uint4 u1 = hin[(size_t)e1.x * 64 + t];
        uint4 u2 = hin[(size_t)e2.x * 64 + t];
        uint4 u3 = hin[(size_t)e3.x * 64 + t];
        accum8(acc, u0, __int_as_float(e0.y));
        accum8(acc, u1, __int_as_float(e1.y));
        accum8(acc, u2, __int_as_float(e2.y));
        accum8(acc, u3, __int_as_float(e3.y));
    }
    for (; j < end; j++) {
        int2 e = g_edge[j];
        uint4 u = hin[(size_t)e.x * 64 + t];
        accum8(acc, u, __int_as_float(e.y));
    }

    if (step == 4) {
        uint4 hi, lo;
        unsigned* hp = &hi.x; unsigned* lp = &lo.x;
#pragma unroll
        for (int q = 0; q < 4; q++) {
            float a = acc[2 * q], b = acc[2 * q + 1];
            float ah = __bfloat162float(__float2bfloat16(a));
            float bh = __bfloat162float(__float2bfloat16(b));
            hp[q] = pack_bf16(a, b);
            lp[q] = pack_bf16(a - ah, b - bh);
        }
        g_h_hi4[self_idx] = hi;
        g_h_lo4[self_idx] = lo;
    } else {
        uint4 o;
        o.x = pack_f16(acc[0], acc[1]);
        o.y = pack_f16(acc[2], acc[3]);
        o.z = pack_f16(acc[4], acc[5]);
        o.w = pack_f16(acc[6], acc[7]);
        hout[self_idx] = o;
    }
}

// ---- weight conversions (after SpMM, before GEMM): which 2=W_t, 3=W_r ----
__global__ void k_conv(int which, const float* __restrict__ ext, int n8) {
    int i = blockIdx.x * blockDim.x + threadIdx.x;
    if (i >= n8) return;
    uint4 *hi, *lo;
    if (which == 2) { hi = g_wt_hi4; lo = g_wt_lo4; }
    else            { hi = g_wr_hi4; lo = g_wr_lo4; }
    float4 v0 = ((const float4*)ext)[2 * i];
    float4 v1 = ((const float4*)ext)[2 * i + 1];
    float f[8] = {v0.x, v0.y, v0.z, v0.w, v1.x, v1.y, v1.z, v1.w};
    uint4 bhi, blo;
    unsigned* hb = &bhi.x; unsigned* lb = &blo.x;
#pragma unroll
    for (int q = 0; q < 4; q++) {
        float a = f[2 * q], b = f[2 * q + 1];
        float ah = __bfloat162float(__float2bfloat16(a));
        float bh = __bfloat162float(__float2bfloat16(b));
        hb[q] = pack_bf16(a, b);
        lb[q] = pack_bf16(a - ah, b - bh);
    }
    hi[i] = bhi;
    lo[i] = blo;
}

// ---- chunk loader: 4 bf16 tiles (Ahi,Alo,Bhi,Blo), 128 rows x 32 cols, cp.async ----
__device__ __forceinline__ void load_chunk(uint32_t sb,
                                           const __nv_bfloat16* __restrict__ Ah,
                                           const __nv_bfloat16* __restrict__ Al,
                                           const __nv_bfloat16* __restrict__ Bh,
                                           const __nv_bfloat16* __restrict__ Bl,
                                           int arow0, int brow0, int k0, int t) {
#pragma unroll
    for (int it = 0; it < 2; it++) {
        int s = t + it * 256;
        int row = s >> 2, q = s & 3;
        uint32_t doff = row * ROWB + q * 16;
        int ar = arow0 + row;
        int ok = (ar < N_NODES) ? 16 : 0;
        size_t aoff = (size_t)(ok ? ar : 0) * F + k0 + q * 8;
        size_t boff = (size_t)(brow0 + row) * F + k0 + q * 8;
        cpa16(sb + 0 * TSZ + doff, Ah + aoff, ok);
        cpa16(sb + 1 * TSZ + doff, Al + aoff, ok);
        cpa16(sb + 2 * TSZ + doff, Bh + boff, 16);
        cpa16(sb + 3 * TSZ + doff, Bl + boff, 16);
    }
}

// ---- fused dual GEMM: out = relu(h@Wt^T + b) + x@Wr^T (split-bf16, 3-pass) ----
__global__ __launch_bounds__(256, 2) void k_gemm2(const float* __restrict__ bias,
                                                  float* __restrict__ out) {
    extern __shared__ char smd[];
    int t = threadIdx.x, lane = t & 31, wid = t >> 5;
    int wm = wid >> 1, wn = wid & 1;
    int bm = blockIdx.x, bn = blockIdx.y;

    int lr8 = lane & 7, lt = lane >> 3;
    int row_off = lr8 + (lt & 1) * 8;
    int col_off = (lt >> 1) * 8;

    const __nv_bfloat16* Hh = (const __nv_bfloat16*)g_h_hi4;
    const __nv_bfloat16* Hl = (const __nv_bfloat16*)g_h_lo4;
    const __nv_bfloat16* Xh = (const __nv_bfloat16*)g_x_hi4;
    const __nv_bfloat16* Xl = (const __nv_bfloat16*)g_x_lo4;
    const __nv_bfloat16* Th = (const __nv_bfloat16*)g_wt_hi4;
    const __nv_bfloat16* Tl = (const __nv_bfloat16*)g_wt_lo4;
    const __nv_bfloat16* Rh = (const __nv_bfloat16*)g_wr_hi4;
    const __nv_bfloat16* Rl = (const __nv_bfloat16*)g_wr_lo4;

    float acc[2][8][4];
#pragma unroll
    for (int i = 0; i < 2; i++)
#pragma unroll
        for (int j = 0; j < 8; j++)
#pragma unroll
            for (int q = 0; q < 4; q++) acc[i][j][q] = 0.f;

    uint32_t sbase = smem_u32(smd);
    int am0 = bm * TILE_M, bn0 = bn * TILE_N;

    load_chunk(sbase, Hh, Hl, Th, Tl, am0, bn0, 0, t);
    cpa_commit();

    for (int c = 0; c < 2 * NCH1; c++) {
        cpa_wait0();
        __syncthreads();
        if (c + 1 < 2 * NCH1) {
            int cn = c + 1;
            uint32_t nsb = sbase + (cn & 1) * BUF_SZ;
            if (cn < NCH1)
                load_chunk(nsb, Hh, Hl, Th, Tl, am0, bn0, cn * KCHUNK, t);
            else
                load_chunk(nsb, Xh, Xl, Rh, Rl, am0, bn0, (cn - NCH1) * KCHUNK, t);
            cpa_commit();
        }
        uint32_t sb = sbase + (c & 1) * BUF_SZ;
#pragma unroll
        for (int pass = 0; pass < 3; pass++) {
            uint32_t aBase = sb + ((pass == 2) ? TSZ : 0);
            uint32_t bBase = sb + 2 * TSZ + ((pass == 1) ? TSZ : 0);
#pragma unroll
            for (int ks = 0; ks < 2; ks++) {
                unsigned af[2][4];
#pragma unroll
                for (int mt = 0; mt < 2; mt++)
                    ldsm4(af[mt], aBase + (wm * 32 + mt * 16 + row_off) * ROWB
                                        + (ks * 16 + col_off) * 2);
                unsigned bf[4][4];
#pragma unroll
                for (int pr = 0; pr < 4; pr++)
                    ldsm4(bf[pr], bBase + (wn * 64 + pr * 16 + row_off) * ROWB
                                        + (ks * 16 + col_off) * 2);
#pragma unroll
                for (int mt = 0; mt < 2; mt++)
#pragma unroll
                    for (int nt = 0; nt < 8; nt++) {
                        int pr = nt >> 1, h = nt & 1;
                        mma_bf16(acc[mt][nt], af[mt], bf[pr][h], bf[pr][h + 2]);
                    }
            }
        }
        if (c == NCH1 - 1) {
            int cb = bn0 + wn * 64 + 2 * (lane & 3);
#pragma unroll
            for (int nt = 0; nt < 8; nt++) {
                float b0 = __ldg(bias + cb + nt * 8);
                float b1 = __ldg(bias + cb + nt * 8 + 1);
#pragma unroll
                for (int mt = 0; mt < 2; mt++) {
                    acc[mt][nt][0] = fmaxf(acc[mt][nt][0] + b0, 0.f);
                    acc[mt][nt][1] = fmaxf(acc[mt][nt][1] + b1, 0.f);
                    acc[mt][nt][2] = fmaxf(acc[mt][nt][2] + b0, 0.f);
                    acc[mt][nt][3] = fmaxf(acc[mt][nt][3] + b1, 0.f);
                }
            }
        }
        __syncthreads();
    }

    int rbase = am0 + wm * 32 + (lane >> 2);
    int cbase = bn0 + wn * 64 + 2 * (lane & 3);
#pragma unroll
    for (int mt = 0; mt < 2; mt++) {
#pragma unroll
        for (int h = 0; h < 2; h++) {
            int row = rbase + mt * 16 + h * 8;
            if (row >= N_NODES) continue;
            float* crow = out + (size_t)row * F;
#pragma unroll
            for (int nt = 0; nt < 8; nt++) {
                int col = cbase + nt * 8;
                *(float2*)(crow + col) = make_float2(acc[mt][nt][2 * h], acc[mt][nt][2 * h + 1]);
            }
        }
    }
}

// ---- row LayerNorm in place ----
__global__ __launch_bounds__(128) void k_ln(float* __restrict__ out,
                                            const float* __restrict__ gamma,
                                            const float* __restrict__ beta) {
    int n = blockIdx.x;
    int t = threadIdx.x;
    float4* row = (float4*)(out + (size_t)n * F);
    float4 v = row[t];
    float s = v.x + v.y + v.z + v.w;
    float q = v.x * v.x + v.y * v.y + v.z * v.z + v.w * v.w;
#pragma unroll
    for (int o = 16; o; o >>= 1) {
        s += __shfl_xor_sync(0xffffffffu, s, o);
        q += __shfl_xor_sync(0xffffffffu, q, o);
    }
    __shared__ float shs[4], shq[4];
    int w = t >> 5, l = t & 31;
    if (l == 0) { shs[w] = s; shq[w] = q; }
    __syncthreads();
    s = shs[0] + shs[1] + shs[2] + shs[3];
    q = shq[0] + shq[1] + shq[2] + shq[3];
    float mu = s * (1.f / F);
    float var = q * (1.f / F) - mu * mu;
    float inv = rsqrtf(var + LN_EPS);
    float4 gv = ((const float4*)gamma)[t];
    float4 bv = ((const float4*)beta)[t];
    v.x = (v.x - mu) * inv * gv.x + bv.x;
    v.y = (v.y - mu) * inv * gv.y + bv.y;
    v.z = (v.z - mu) * inv * gv.z + bv.z;
    v.w = (v.w - mu) * inv * gv.w + bv.w;
    row[t] = v;
}

extern "C" void kernel_launch(void* const* d_in, const int* in_sizes, int n_in,
                              void* d_out, int out_size) {
    const float* x = (const float*)d_in[0];
    const int* ei = (const int*)d_in[1];
    const float* ts = (const float*)d_in[2];
    const float* W_t = (const float*)d_in[3];
    const float* b_t = (const float*)d_in[4];
    const float* W_r = (const float*)d_in[5];
    const float* gamma = (const float*)d_in[6];
    const float* beta = (const float*)d_in[7];
    const void* gt = d_in[8];
    float* out = (float*)d_out;

    cudaFuncSetAttribute(k_gemm2, cudaFuncAttributeMaxDynamicSharedMemorySize, SMEM_DYN);

    // launch order chosen so ncu (-s 5 -c 1) captures k_spmm16 step 0
    k_initconv<<<(NF8 + 255) / 256, 256>>>(x, gt);          // 0
    k_pass1w<<<N_EDGES / 256, 256>>>(ei, ts);               // 1
    k_dinv<<<(N_NODES + 255) / 256, 256>>>(gt);             // 2
    k_scan<<<1, 1024>>>();                                  // 3
    k_fill<<<N_EDGES / 256, 256>>>(ei);                     // 4
    for (int s = 0; s < 5; s++)                             // 5..9
        k_spmm16<<<N_NODES, 64>>>(s, gt);
    k_conv<<<(WF8 + 255) / 256, 256>>>(2, W_t, WF8);        // 10
    k_conv<<<(WF8 + 255) / 256, 256>>>(3, W_r, WF8);        // 11
    dim3 gg((N_NODES + TILE_M - 1) / TILE_M, F / TILE_N);
    k_gemm2<<<gg, 256, SMEM_DYN>>>(b_t, out);               // 12
    k_ln<<<N_NODES, 128>>>(out, gamma, beta);               // 13
}